// round 9
// baseline (speedup 1.0000x reference)
#include <cuda_runtime.h>
#include <cuda_fp16.h>
#include <math.h>
#include <stdint.h>

// Problem constants
#define NB        8
#define CD        64
#define HH        4096
#define NPTS      (NB*HH)    // 32768
#define NCODE     8192
#define ZQ_ELEMS  (NB*CD*HH) // 2097152

// Output layout (flat float32): [z_q | loss | indices | perplexity]
#define OUT_ZQ    0
#define OUT_LOSS  ZQ_ELEMS
#define OUT_IDX   (ZQ_ELEMS + 1)
#define OUT_PERP  (ZQ_ELEMS + 1 + NPTS)

#define DELTA     1e-4f      // prune window; >= 4x worst-case approx error

// B fragments (hi fp16 only) for mma.m16n8k16: [nf(1024)][kc(4)][lane(32)]
// uint2 = (pack(b0k0,b0k1), pack(b1k0,b1k1)); B[k][n] = 2*E[n][k].
__device__ uint2  g_BfragH[1024 * 4 * 32];  // 1 MB
__device__ float  g_enorm[NCODE];
__device__ float  g_nzn[NPTS];              // -|z|^2 per row (exact chain)
__device__ float  g_cval[NPTS * 8];         // top-2 approx values x 4 lanes
__device__ int    g_cidx[NPTS * 8];
__device__ float  g_rowM[NPTS];             // approx row max
__device__ int    g_rflag[NPTS];            // fallback flag
__device__ int    g_idx[NPTS];
__device__ int    g_hist[NCODE];
__device__ float  g_partial[2048];

// ---------------------------------------------------------------------------
__device__ __forceinline__ uint32_t pack_h2(__half a, __half b) {
    __half2 h = __halves2half2(a, b);
    return *(uint32_t*)&h;
}

__device__ __forceinline__ void mma_f16(float& d0, float& d1, float& d2, float& d3,
                                        uint32_t a0, uint32_t a1, uint32_t a2, uint32_t a3,
                                        uint32_t b0, uint32_t b1) {
    asm volatile(
        "mma.sync.aligned.m16n8k16.row.col.f32.f16.f16.f32 "
        "{%0,%1,%2,%3},{%4,%5,%6,%7},{%8,%9},{%0,%1,%2,%3};"
        : "+f"(d0), "+f"(d1), "+f"(d2), "+f"(d3)
        : "r"(a0), "r"(a1), "r"(a2), "r"(a3), "r"(b0), "r"(b1));
}

__device__ __forceinline__ void cp_async16(uint32_t saddr, const void* gptr) {
    asm volatile("cp.async.cg.shared.global [%0], [%1], 16;" :: "r"(saddr), "l"(gptr));
}

// ---------------------------------------------------------------------------
// Prep A: |e|^2 (reference rounding chain) + zero histogram
// ---------------------------------------------------------------------------
__global__ void vq_prep(const float* __restrict__ E) {
    int idx = blockIdx.x * 256 + threadIdx.x;
    if (idx < NCODE) {
        const float* r = E + idx * CD;
        float s = 0.f;
#pragma unroll
        for (int d = 0; d < CD; d++) s = __fadd_rn(s, __fmul_rn(r[d], r[d]));
        g_enorm[idx] = s;
        g_hist[idx] = 0;
    }
}

// ---------------------------------------------------------------------------
// Prep B: pack codebook hi-fp16 fragments of 2E. grid 512 x 256.
// ---------------------------------------------------------------------------
__global__ void vq_prep_bfrag(const float* __restrict__ E) {
    int idx = blockIdx.x * 256 + threadIdx.x;     // [nf*4+kc]*32 + lane
    int lane = idx & 31;
    int kc = (idx >> 5) & 3;
    int nf = idx >> 7;
    int n = nf * 8 + (lane >> 2);
    int k0 = kc * 16 + (lane & 3) * 2;
    const float* r = E + n * CD;
    __half h0 = __float2half_rn(2.0f * r[k0]);
    __half h1 = __float2half_rn(2.0f * r[k0 + 1]);
    __half h2 = __float2half_rn(2.0f * r[k0 + 8]);
    __half h3 = __float2half_rn(2.0f * r[k0 + 9]);
    uint2 v;
    v.x = pack_h2(h0, h1);
    v.y = pack_h2(h2, h3);
    g_BfragH[idx] = v;
}

// ---------------------------------------------------------------------------
// Phase 1: single-pass fp16 approx GEMM + branchless per-lane top-2.
// CTA: 256 threads = 8 warps; warp w owns rows [blk*256 + w*32, +32).
// grid 128.
// ---------------------------------------------------------------------------
__global__ void __launch_bounds__(256, 1) vq_scan(const float* __restrict__ z) {
    __shared__ uint2 Bs[2][512];     // 8 KB double buffer (n-tile of 32 codes)

    const int tid = threadIdx.x;
    const int lane = tid & 31;
    const int w = tid >> 5;
    const int blk = blockIdx.x;
    const int b = (blk * 256) >> 12;
    const int hb = (blk * 256) & (HH - 1);
    const float* zb = z + b * (CD * HH);
    const int hw = hb + w * 32;
    const int Wrow = blk * 256 + w * 32;

    // ---- exact -|z|^2 per row (reference sequential chain); lane l -> row hw+l
    {
        float s = 0.f;
        int h = hw + lane;
#pragma unroll
        for (int k = 0; k < CD; k++) {
            float v = zb[k * HH + h];
            s = __fadd_rn(s, __fmul_rn(v, v));
        }
        g_nzn[Wrow + lane] = -s;
    }

    // ---- A fragments (hi fp16 only), resident for whole N sweep
    uint32_t Ahi[2][4][4];
#pragma unroll
    for (int mf = 0; mf < 2; mf++) {
        int r0 = hw + mf * 16 + (lane >> 2);
        int r1 = r0 + 8;
#pragma unroll
        for (int kc = 0; kc < 4; kc++) {
            int k0 = kc * 16 + (lane & 3) * 2;
#pragma unroll
            for (int q = 0; q < 4; q++) {
                int rr = (q & 1) ? r1 : r0;
                int kk = k0 + ((q & 2) ? 8 : 0);
                __half hA = __float2half_rn(zb[kk * HH + rr]);
                __half hB = __float2half_rn(zb[(kk + 1) * HH + rr]);
                Ahi[mf][kc][q] = pack_h2(hA, hB);
            }
        }
    }

    // top-2 per (mf, rr) slot -- plain scalar registers, branchless updates
    float b0v[2][2], b1v[2][2];
    int   b0i[2][2], b1i[2][2];
#pragma unroll
    for (int mf = 0; mf < 2; mf++)
#pragma unroll
        for (int rr = 0; rr < 2; rr++) {
            b0v[mf][rr] = -3.4e38f; b1v[mf][rr] = -3.4e38f;
            b0i[mf][rr] = 0;        b1i[mf][rr] = 0;
        }

    const int NT = NCODE / 32;   // 256 n-tiles

    // prologue: stage tile 0 (512 uint2 = 256 x 16B; 1 cp per thread)
    {
        uint32_t sa = (uint32_t)__cvta_generic_to_shared(&Bs[0][tid * 2]);
        cp_async16(sa, &g_BfragH[tid * 2]);
        asm volatile("cp.async.commit_group;" ::: "memory");
    }

#pragma unroll 1
    for (int t = 0; t < NT; t++) {
        const int cur = t & 1;
        if (t + 1 < NT) {
            const int nxt = cur ^ 1;
            uint32_t sa = (uint32_t)__cvta_generic_to_shared(&Bs[nxt][tid * 2]);
            cp_async16(sa, &g_BfragH[(t + 1) * 512 + tid * 2]);
            asm volatile("cp.async.commit_group;" ::: "memory");
            asm volatile("cp.async.wait_group 1;" ::: "memory");
        } else {
            asm volatile("cp.async.wait_group 0;" ::: "memory");
        }
        __syncthreads();

        float Dh[2][4][4];
#pragma unroll
        for (int mf = 0; mf < 2; mf++)
#pragma unroll
            for (int nf = 0; nf < 4; nf++)
#pragma unroll
                for (int c = 0; c < 4; c++) Dh[mf][nf][c] = 0.f;

#pragma unroll
        for (int kc = 0; kc < 4; kc++) {
            uint2 bq[4];
#pragma unroll
            for (int nf = 0; nf < 4; nf++)
                bq[nf] = Bs[cur][(nf * 4 + kc) * 32 + lane];
#pragma unroll
            for (int mf = 0; mf < 2; mf++)
#pragma unroll
                for (int nf = 0; nf < 4; nf++)
                    mma_f16(Dh[mf][nf][0], Dh[mf][nf][1], Dh[mf][nf][2], Dh[mf][nf][3],
                            Ahi[mf][kc][0], Ahi[mf][kc][1], Ahi[mf][kc][2], Ahi[mf][kc][3],
                            bq[nf].x, bq[nf].y);
        }
        __syncthreads();

        // epilogue: u = Dh - en; branchless top-2 insertion per slot
        const int nbase = t * 32;
#pragma unroll
        for (int nf = 0; nf < 4; nf++) {
            const int ncol = nbase + nf * 8 + (lane & 3) * 2;
            float2 en2 = *(const float2*)(g_enorm + ncol);
#pragma unroll
            for (int mf = 0; mf < 2; mf++) {
#pragma unroll
                for (int c = 0; c < 4; c++) {
                    const int rr = c >> 1;
                    float u = Dh[mf][nf][c] - ((c & 1) ? en2.y : en2.x);
                    int ix = ncol + (c & 1);
                    bool t0 = u > b0v[mf][rr];
                    bool t1 = u > b1v[mf][rr];
                    float nb1 = t0 ? b0v[mf][rr] : (t1 ? u : b1v[mf][rr]);
                    int   ni1 = t0 ? b0i[mf][rr] : (t1 ? ix : b1i[mf][rr]);
                    b0v[mf][rr] = t0 ? u : b0v[mf][rr];
                    b0i[mf][rr] = t0 ? ix : b0i[mf][rr];
                    b1v[mf][rr] = nb1;
                    b1i[mf][rr] = ni1;
                }
            }
        }
    }

    // per (mf, rr): quad row max, fallback flag, store candidates
#pragma unroll
    for (int mf = 0; mf < 2; mf++)
#pragma unroll
        for (int rr = 0; rr < 2; rr++) {
            float M = b0v[mf][rr];
#pragma unroll
            for (int off = 1; off <= 2; off <<= 1)
                M = fmaxf(M, __shfl_xor_sync(0xffffffffu, M, off));
            int f = (b1v[mf][rr] >= M - DELTA) ? 1 : 0;
#pragma unroll
            for (int off = 1; off <= 2; off <<= 1)
                f |= __shfl_xor_sync(0xffffffffu, f, off);
            int row = Wrow + mf * 16 + (lane >> 2) + rr * 8;
            int base = row * 8 + (lane & 3) * 2;
            g_cval[base] = b0v[mf][rr];
            g_cidx[base] = b0i[mf][rr];
            g_cval[base + 1] = b1v[mf][rr];
            g_cidx[base + 1] = b1i[mf][rr];
            if ((lane & 3) == 0) {
                g_rowM[row] = M;
                g_rflag[row] = f;
            }
        }
}

// ---------------------------------------------------------------------------
// Phase 2: exact verification of candidates (reference rounding chain).
// 1 warp per row; grid NPTS/8 x 256.
// ---------------------------------------------------------------------------
__global__ void __launch_bounds__(256) vq_verify(const float* __restrict__ z,
                                                 const float* __restrict__ E) {
    __shared__ float zsh[8][64];
    const int lane = threadIdx.x & 31;
    const int wid = threadIdx.x >> 5;
    const int row = blockIdx.x * 8 + wid;
    const int b = row >> 12;
    const int h = row & (HH - 1);
    const float* zrow = z + b * (CD * HH) + h;

    zsh[wid][lane] = zrow[lane * HH];
    zsh[wid][lane + 32] = zrow[(lane + 32) * HH];
    __syncwarp();

    const float nzn = g_nzn[row];
    float bestv = -3.4e38f;
    int   besti = 0x7fffffff;

    if (!g_rflag[row]) {
        const float M = g_rowM[row];
        if (lane < 8) {
            float u = g_cval[row * 8 + lane];
            int ix = g_cidx[row * 8 + lane];
            if (u >= M - DELTA) {
                const float* er = E + ix * CD;
                float dot = 0.f;
#pragma unroll
                for (int k = 0; k < CD; k++)
                    dot = __fmaf_rn(zsh[wid][k], 2.0f * er[k], dot);
                bestv = __fadd_rn(__fadd_rn(nzn, -g_enorm[ix]), dot);
                besti = ix;
            }
        }
    } else {
        // exact full rescan (rare): lanes stride the codebook, ascending n
        for (int n = lane; n < NCODE; n += 32) {
            const float* er = E + n * CD;
            float dot = 0.f;
#pragma unroll
            for (int k = 0; k < CD; k++)
                dot = __fmaf_rn(zsh[wid][k], 2.0f * er[k], dot);
            float d = __fadd_rn(__fadd_rn(nzn, -g_enorm[n]), dot);
            if (d > bestv) { bestv = d; besti = n; }
        }
    }

    // warp argmax with first-index tie-break
#pragma unroll
    for (int off = 16; off > 0; off >>= 1) {
        float ov = __shfl_xor_sync(0xffffffffu, bestv, off);
        int   oi = __shfl_xor_sync(0xffffffffu, besti, off);
        if (ov > bestv || (ov == bestv && oi < besti)) { bestv = ov; besti = oi; }
    }
    if (lane == 0) g_idx[row] = besti;
}

// ---------------------------------------------------------------------------
// Gather z_q (straight-through rounding emulated) + SSD partial.
// ---------------------------------------------------------------------------
__global__ void vq_gather(const float* __restrict__ z, const float* __restrict__ E,
                          float* __restrict__ out) {
    __shared__ float red[256];
    int tid = threadIdx.x;
    int base = (blockIdx.x * 256 + tid) * 4;
    int h = base & (HH - 1);
    int c = (base >> 12) & (CD - 1);
    int b = base >> 18;
    const int* gi = g_idx + b * HH + h;
    float4 zv = *(const float4*)(z + base);
    float e0 = E[gi[0] * CD + c];
    float e1 = E[gi[1] * CD + c];
    float e2 = E[gi[2] * CD + c];
    float e3 = E[gi[3] * CD + c];
    float d0 = __fadd_rn(e0, -zv.x);
    float d1 = __fadd_rn(e1, -zv.y);
    float d2 = __fadd_rn(e2, -zv.z);
    float d3 = __fadd_rn(e3, -zv.w);
    // straight-through: out = fl(z + fl(e - z))
    float4 o;
    o.x = __fadd_rn(zv.x, d0);
    o.y = __fadd_rn(zv.y, d1);
    o.z = __fadd_rn(zv.z, d2);
    o.w = __fadd_rn(zv.w, d3);
    *(float4*)(out + OUT_ZQ + base) = o;
    red[tid] = d0 * d0 + d1 * d1 + d2 * d2 + d3 * d3;
    __syncthreads();
    for (int off = 128; off > 0; off >>= 1) {
        if (tid < off) red[tid] += red[tid + off];
        __syncthreads();
    }
    if (tid == 0) g_partial[blockIdx.x] = red[0];
}

// ---------------------------------------------------------------------------
__global__ void vq_hist(float* __restrict__ out) {
    int n = blockIdx.x * 256 + threadIdx.x;
    int idx = g_idx[n];
    atomicAdd(&g_hist[idx], 1);
    out[OUT_IDX + n] = (float)idx;
}

// ---------------------------------------------------------------------------
__global__ void vq_final(float* __restrict__ out) {
    __shared__ float red[256];
    int tid = threadIdx.x;

    float s = 0.f;
    for (int i = tid; i < 2048; i += 256) s += g_partial[i];
    red[tid] = s;
    __syncthreads();
    for (int off = 128; off > 0; off >>= 1) {
        if (tid < off) red[tid] += red[tid + off];
        __syncthreads();
    }
    if (tid == 0)
        out[OUT_LOSS] = 1.25f * red[0] / (float)ZQ_ELEMS;
    __syncthreads();

    float ent = 0.f;
    for (int i = tid; i < NCODE; i += 256) {
        float p = (float)g_hist[i] * (1.f / (float)NPTS);
        ent += p * logf(p + 1e-10f);
    }
    red[tid] = ent;
    __syncthreads();
    for (int off = 128; off > 0; off >>= 1) {
        if (tid < off) red[tid] += red[tid + off];
        __syncthreads();
    }
    if (tid == 0) out[OUT_PERP] = expf(-red[0]);
}

// ---------------------------------------------------------------------------
extern "C" void kernel_launch(void* const* d_in, const int* in_sizes, int n_in,
                              void* d_out, int out_size) {
    const float* z = (const float*)d_in[0];        // (8, 64, 4096) f32
    const float* E = (const float*)d_in[1];        // (8192, 64) f32
    float* out = (float*)d_out;

    vq_prep      <<<32, 256>>>(E);
    vq_prep_bfrag<<<512, 256>>>(E);
    vq_scan      <<<128, 256>>>(z);
    vq_verify    <<<NPTS / 8, 256>>>(z, E);
    vq_gather    <<<2048, 256>>>(z, E, out);
    vq_hist      <<<NPTS / 256, 256>>>(out);
    vq_final     <<<1, 256>>>(out);
}

// round 10
// speedup vs baseline: 4.4767x; 4.4767x over previous
#include <cuda_runtime.h>
#include <cuda_fp16.h>
#include <math.h>
#include <stdint.h>

// Problem constants
#define NB        8
#define CD        64
#define HH        4096
#define NPTS      (NB*HH)    // 32768
#define NCODE     8192
#define ZQ_ELEMS  (NB*CD*HH) // 2097152

// Output layout (flat float32): [z_q | loss | indices | perplexity]
#define OUT_ZQ    0
#define OUT_LOSS  ZQ_ELEMS
#define OUT_IDX   (ZQ_ELEMS + 1)
#define OUT_PERP  (ZQ_ELEMS + 1 + NPTS)

#define DELTA     1e-4f      // prune window; >= 4x worst-case approx error

// B fragments (hi fp16 only) for mma.m16n8k16: [nf(1024)][kc(4)][lane(32)]
// uint2 = (pack(b0k0,b0k1), pack(b1k0,b1k1)); B[k][n] = 2*E[n][k].
__device__ uint2  g_BfragH[1024 * 4 * 32];  // 1 MB
__device__ float  g_enorm[NCODE];
__device__ float  g_nzn[NPTS];              // -|z|^2 per row (exact chain)
__device__ float  g_cval[NPTS * 12];        // top-3 approx values x 4 lanes
__device__ int    g_cidx[NPTS * 12];
__device__ float  g_rowM[NPTS];             // approx row max
__device__ int    g_rflag[NPTS];            // fallback flag
__device__ int    g_idx[NPTS];
__device__ int    g_hist[NCODE];
__device__ float  g_partial[2048];

// ---------------------------------------------------------------------------
__device__ __forceinline__ uint32_t pack_h2(__half a, __half b) {
    __half2 h = __halves2half2(a, b);
    return *(uint32_t*)&h;
}

__device__ __forceinline__ void mma_f16(float& d0, float& d1, float& d2, float& d3,
                                        uint32_t a0, uint32_t a1, uint32_t a2, uint32_t a3,
                                        uint32_t b0, uint32_t b1) {
    asm volatile(
        "mma.sync.aligned.m16n8k16.row.col.f32.f16.f16.f32 "
        "{%0,%1,%2,%3},{%4,%5,%6,%7},{%8,%9},{%0,%1,%2,%3};"
        : "+f"(d0), "+f"(d1), "+f"(d2), "+f"(d3)
        : "r"(a0), "r"(a1), "r"(a2), "r"(a3), "r"(b0), "r"(b1));
}

__device__ __forceinline__ void cp_async16(uint32_t saddr, const void* gptr) {
    asm volatile("cp.async.cg.shared.global [%0], [%1], 16;" :: "r"(saddr), "l"(gptr));
}

// Pair-reduce two adjacent-column values then top-3 insert (named scalars only).
// dmx accumulates discarded pair-minima for the containment guard.
#define TOP3_PAIR(U0, U1, IX0, B0V, B0I, B1V, B1I, B2V, B2I, DMX) do {        \
    float _u0 = (U0), _u1 = (U1);                                             \
    float _pmx = fmaxf(_u0, _u1);                                             \
    float _pmn = fminf(_u0, _u1);                                             \
    int   _pix = (_u0 >= _u1) ? (IX0) : ((IX0) + 1);                          \
    DMX = fmaxf(DMX, _pmn);                                                   \
    bool _g0 = _pmx > B0V;                                                    \
    bool _g1 = _pmx > B1V;                                                    \
    bool _g2 = _pmx > B2V;                                                    \
    B2V = _g1 ? B1V : (_g2 ? _pmx : B2V);                                     \
    B2I = _g1 ? B1I : (_g2 ? _pix : B2I);                                     \
    B1V = _g0 ? B0V : (_g1 ? _pmx : B1V);                                     \
    B1I = _g0 ? B0I : (_g1 ? _pix : B1I);                                     \
    B0V = _g0 ? _pmx : B0V;                                                   \
    B0I = _g0 ? _pix : B0I;                                                   \
} while (0)

// Finalize one slot: quad row-max, flag, candidate store.
#define SLOT_FINISH(MF, RR, B0V, B0I, B1V, B1I, B2V, B2I, DMX) do {           \
    float _M = B0V;                                                           \
    _M = fmaxf(_M, __shfl_xor_sync(0xffffffffu, _M, 1));                      \
    _M = fmaxf(_M, __shfl_xor_sync(0xffffffffu, _M, 2));                      \
    int _f = (fmaxf(B2V, DMX) >= _M - DELTA) ? 1 : 0;                         \
    _f |= __shfl_xor_sync(0xffffffffu, _f, 1);                                \
    _f |= __shfl_xor_sync(0xffffffffu, _f, 2);                                \
    int _row = Wrow + (MF) * 16 + (lane >> 2) + (RR) * 8;                     \
    int _base = _row * 12 + (lane & 3) * 3;                                   \
    g_cval[_base]     = B0V;  g_cidx[_base]     = B0I;                        \
    g_cval[_base + 1] = B1V;  g_cidx[_base + 1] = B1I;                        \
    g_cval[_base + 2] = B2V;  g_cidx[_base + 2] = B2I;                        \
    if ((lane & 3) == 0) { g_rowM[_row] = _M; g_rflag[_row] = _f; }           \
} while (0)

// ---------------------------------------------------------------------------
// Prep A: |e|^2 (reference rounding chain) + zero histogram
// ---------------------------------------------------------------------------
__global__ void vq_prep(const float* __restrict__ E) {
    int idx = blockIdx.x * 256 + threadIdx.x;
    if (idx < NCODE) {
        const float* r = E + idx * CD;
        float s = 0.f;
#pragma unroll
        for (int d = 0; d < CD; d++) s = __fadd_rn(s, __fmul_rn(r[d], r[d]));
        g_enorm[idx] = s;
        g_hist[idx] = 0;
    }
}

// ---------------------------------------------------------------------------
// Prep B: pack codebook hi-fp16 fragments of 2E. grid 512 x 256.
// ---------------------------------------------------------------------------
__global__ void vq_prep_bfrag(const float* __restrict__ E) {
    int idx = blockIdx.x * 256 + threadIdx.x;     // [nf*4+kc]*32 + lane
    int lane = idx & 31;
    int kc = (idx >> 5) & 3;
    int nf = idx >> 7;
    int n = nf * 8 + (lane >> 2);
    int k0 = kc * 16 + (lane & 3) * 2;
    const float* r = E + n * CD;
    __half h0 = __float2half_rn(2.0f * r[k0]);
    __half h1 = __float2half_rn(2.0f * r[k0 + 1]);
    __half h2 = __float2half_rn(2.0f * r[k0 + 8]);
    __half h3 = __float2half_rn(2.0f * r[k0 + 9]);
    uint2 v;
    v.x = pack_h2(h0, h1);
    v.y = pack_h2(h2, h3);
    g_BfragH[idx] = v;
}

// ---------------------------------------------------------------------------
// Phase 1: single-pass fp16 approx GEMM + named-scalar top-3 tracking.
// CTA: 256 threads = 8 warps; warp w owns rows [blk*256 + w*32, +32).
// grid 128.
// ---------------------------------------------------------------------------
__global__ void __launch_bounds__(256, 1) vq_scan(const float* __restrict__ z) {
    __shared__ uint2 Bs[2][512];     // 8 KB double buffer (n-tile of 32 codes)

    const int tid = threadIdx.x;
    const int lane = tid & 31;
    const int w = tid >> 5;
    const int blk = blockIdx.x;
    const int b = (blk * 256) >> 12;
    const int hb = (blk * 256) & (HH - 1);
    const float* zb = z + b * (CD * HH);
    const int hw = hb + w * 32;
    const int Wrow = blk * 256 + w * 32;

    // ---- exact -|z|^2 per row (reference sequential chain); lane l -> row hw+l
    {
        float s = 0.f;
        int h = hw + lane;
#pragma unroll
        for (int k = 0; k < CD; k++) {
            float v = zb[k * HH + h];
            s = __fadd_rn(s, __fmul_rn(v, v));
        }
        g_nzn[Wrow + lane] = -s;
    }

    // ---- A fragments (hi fp16 only), resident for whole N sweep
    uint32_t Ahi[2][4][4];
#pragma unroll
    for (int mf = 0; mf < 2; mf++) {
        int r0 = hw + mf * 16 + (lane >> 2);
        int r1 = r0 + 8;
#pragma unroll
        for (int kc = 0; kc < 4; kc++) {
            int k0 = kc * 16 + (lane & 3) * 2;
#pragma unroll
            for (int q = 0; q < 4; q++) {
                int rr = (q & 1) ? r1 : r0;
                int kk = k0 + ((q & 2) ? 8 : 0);
                __half hA = __float2half_rn(zb[kk * HH + rr]);
                __half hB = __float2half_rn(zb[(kk + 1) * HH + rr]);
                Ahi[mf][kc][q] = pack_h2(hA, hB);
            }
        }
    }

    // top-3 trackers: NAMED SCALARS (slot = mf,rr)
    float b0v00 = -3.4e38f, b1v00 = -3.4e38f, b2v00 = -3.4e38f, dmx00 = -3.4e38f;
    float b0v01 = -3.4e38f, b1v01 = -3.4e38f, b2v01 = -3.4e38f, dmx01 = -3.4e38f;
    float b0v10 = -3.4e38f, b1v10 = -3.4e38f, b2v10 = -3.4e38f, dmx10 = -3.4e38f;
    float b0v11 = -3.4e38f, b1v11 = -3.4e38f, b2v11 = -3.4e38f, dmx11 = -3.4e38f;
    int b0i00 = 0, b1i00 = 0, b2i00 = 0;
    int b0i01 = 0, b1i01 = 0, b2i01 = 0;
    int b0i10 = 0, b1i10 = 0, b2i10 = 0;
    int b0i11 = 0, b1i11 = 0, b2i11 = 0;

    const int NT = NCODE / 32;   // 256 n-tiles

    // prologue: stage tile 0 (512 uint2 = 256 x 16B; 1 cp per thread)
    {
        uint32_t sa = (uint32_t)__cvta_generic_to_shared(&Bs[0][tid * 2]);
        cp_async16(sa, &g_BfragH[tid * 2]);
        asm volatile("cp.async.commit_group;" ::: "memory");
    }

#pragma unroll 1
    for (int t = 0; t < NT; t++) {
        const int cur = t & 1;
        if (t + 1 < NT) {
            const int nxt = cur ^ 1;
            uint32_t sa = (uint32_t)__cvta_generic_to_shared(&Bs[nxt][tid * 2]);
            cp_async16(sa, &g_BfragH[(t + 1) * 512 + tid * 2]);
            asm volatile("cp.async.commit_group;" ::: "memory");
            asm volatile("cp.async.wait_group 1;" ::: "memory");
        } else {
            asm volatile("cp.async.wait_group 0;" ::: "memory");
        }
        __syncthreads();

        float Dh[2][4][4];
#pragma unroll
        for (int mf = 0; mf < 2; mf++)
#pragma unroll
            for (int nf = 0; nf < 4; nf++)
#pragma unroll
                for (int c = 0; c < 4; c++) Dh[mf][nf][c] = 0.f;

#pragma unroll
        for (int kc = 0; kc < 4; kc++) {
            uint2 bq[4];
#pragma unroll
            for (int nf = 0; nf < 4; nf++)
                bq[nf] = Bs[cur][(nf * 4 + kc) * 32 + lane];
#pragma unroll
            for (int mf = 0; mf < 2; mf++)
#pragma unroll
                for (int nf = 0; nf < 4; nf++)
                    mma_f16(Dh[mf][nf][0], Dh[mf][nf][1], Dh[mf][nf][2], Dh[mf][nf][3],
                            Ahi[mf][kc][0], Ahi[mf][kc][1], Ahi[mf][kc][2], Ahi[mf][kc][3],
                            bq[nf].x, bq[nf].y);
        }
        __syncthreads();

        // epilogue: u = Dh - en; pair-reduce + top-3 into named scalars
        const int nbase = t * 32;
#pragma unroll
        for (int nf = 0; nf < 4; nf++) {
            const int ncol = nbase + nf * 8 + (lane & 3) * 2;
            float2 en2 = *(const float2*)(g_enorm + ncol);
            TOP3_PAIR(Dh[0][nf][0] - en2.x, Dh[0][nf][1] - en2.y, ncol,
                      b0v00, b0i00, b1v00, b1i00, b2v00, b2i00, dmx00);
            TOP3_PAIR(Dh[0][nf][2] - en2.x, Dh[0][nf][3] - en2.y, ncol,
                      b0v01, b0i01, b1v01, b1i01, b2v01, b2i01, dmx01);
            TOP3_PAIR(Dh[1][nf][0] - en2.x, Dh[1][nf][1] - en2.y, ncol,
                      b0v10, b0i10, b1v10, b1i10, b2v10, b2i10, dmx10);
            TOP3_PAIR(Dh[1][nf][2] - en2.x, Dh[1][nf][3] - en2.y, ncol,
                      b0v11, b0i11, b1v11, b1i11, b2v11, b2i11, dmx11);
        }
    }

    SLOT_FINISH(0, 0, b0v00, b0i00, b1v00, b1i00, b2v00, b2i00, dmx00);
    SLOT_FINISH(0, 1, b0v01, b0i01, b1v01, b1i01, b2v01, b2i01, dmx01);
    SLOT_FINISH(1, 0, b0v10, b0i10, b1v10, b1i10, b2v10, b2i10, dmx10);
    SLOT_FINISH(1, 1, b0v11, b0i11, b1v11, b1i11, b2v11, b2i11, dmx11);
}

// ---------------------------------------------------------------------------
// Phase 2: exact verification of candidates (reference rounding chain).
// 1 warp per row; grid NPTS/8 x 256.
// ---------------------------------------------------------------------------
__global__ void __launch_bounds__(256) vq_verify(const float* __restrict__ z,
                                                 const float* __restrict__ E) {
    __shared__ float zsh[8][64];
    const int lane = threadIdx.x & 31;
    const int wid = threadIdx.x >> 5;
    const int row = blockIdx.x * 8 + wid;
    const int b = row >> 12;
    const int h = row & (HH - 1);
    const float* zrow = z + b * (CD * HH) + h;

    zsh[wid][lane] = zrow[lane * HH];
    zsh[wid][lane + 32] = zrow[(lane + 32) * HH];
    __syncwarp();

    const float nzn = g_nzn[row];
    float bestv = -3.4e38f;
    int   besti = 0x7fffffff;

    if (!g_rflag[row]) {
        const float M = g_rowM[row];
        if (lane < 12) {
            float u = g_cval[row * 12 + lane];
            int ix = g_cidx[row * 12 + lane];
            if (u >= M - DELTA) {
                const float* er = E + ix * CD;
                float dot = 0.f;
#pragma unroll
                for (int k = 0; k < CD; k++)
                    dot = __fmaf_rn(zsh[wid][k], 2.0f * er[k], dot);
                bestv = __fadd_rn(__fadd_rn(nzn, -g_enorm[ix]), dot);
                besti = ix;
            }
        }
    } else {
        // exact full rescan (rare): lanes stride the codebook, ascending n
        for (int n = lane; n < NCODE; n += 32) {
            const float* er = E + n * CD;
            float dot = 0.f;
#pragma unroll
            for (int k = 0; k < CD; k++)
                dot = __fmaf_rn(zsh[wid][k], 2.0f * er[k], dot);
            float d = __fadd_rn(__fadd_rn(nzn, -g_enorm[n]), dot);
            if (d > bestv) { bestv = d; besti = n; }
        }
    }

    // warp argmax with first-index tie-break
#pragma unroll
    for (int off = 16; off > 0; off >>= 1) {
        float ov = __shfl_xor_sync(0xffffffffu, bestv, off);
        int   oi = __shfl_xor_sync(0xffffffffu, besti, off);
        if (ov > bestv || (ov == bestv && oi < besti)) { bestv = ov; besti = oi; }
    }
    if (lane == 0) g_idx[row] = besti;
}

// ---------------------------------------------------------------------------
// Gather z_q (straight-through rounding emulated) + SSD partial.
// ---------------------------------------------------------------------------
__global__ void vq_gather(const float* __restrict__ z, const float* __restrict__ E,
                          float* __restrict__ out) {
    __shared__ float red[256];
    int tid = threadIdx.x;
    int base = (blockIdx.x * 256 + tid) * 4;
    int h = base & (HH - 1);
    int c = (base >> 12) & (CD - 1);
    int b = base >> 18;
    const int* gi = g_idx + b * HH + h;
    float4 zv = *(const float4*)(z + base);
    float e0 = E[gi[0] * CD + c];
    float e1 = E[gi[1] * CD + c];
    float e2 = E[gi[2] * CD + c];
    float e3 = E[gi[3] * CD + c];
    float d0 = __fadd_rn(e0, -zv.x);
    float d1 = __fadd_rn(e1, -zv.y);
    float d2 = __fadd_rn(e2, -zv.z);
    float d3 = __fadd_rn(e3, -zv.w);
    // straight-through: out = fl(z + fl(e - z))
    float4 o;
    o.x = __fadd_rn(zv.x, d0);
    o.y = __fadd_rn(zv.y, d1);
    o.z = __fadd_rn(zv.z, d2);
    o.w = __fadd_rn(zv.w, d3);
    *(float4*)(out + OUT_ZQ + base) = o;
    red[tid] = d0 * d0 + d1 * d1 + d2 * d2 + d3 * d3;
    __syncthreads();
    for (int off = 128; off > 0; off >>= 1) {
        if (tid < off) red[tid] += red[tid + off];
        __syncthreads();
    }
    if (tid == 0) g_partial[blockIdx.x] = red[0];
}

// ---------------------------------------------------------------------------
__global__ void vq_hist(float* __restrict__ out) {
    int n = blockIdx.x * 256 + threadIdx.x;
    int idx = g_idx[n];
    atomicAdd(&g_hist[idx], 1);
    out[OUT_IDX + n] = (float)idx;
}

// ---------------------------------------------------------------------------
__global__ void vq_final(float* __restrict__ out) {
    __shared__ float red[256];
    int tid = threadIdx.x;

    float s = 0.f;
    for (int i = tid; i < 2048; i += 256) s += g_partial[i];
    red[tid] = s;
    __syncthreads();
    for (int off = 128; off > 0; off >>= 1) {
        if (tid < off) red[tid] += red[tid + off];
        __syncthreads();
    }
    if (tid == 0)
        out[OUT_LOSS] = 1.25f * red[0] / (float)ZQ_ELEMS;
    __syncthreads();

    float ent = 0.f;
    for (int i = tid; i < NCODE; i += 256) {
        float p = (float)g_hist[i] * (1.f / (float)NPTS);
        ent += p * logf(p + 1e-10f);
    }
    red[tid] = ent;
    __syncthreads();
    for (int off = 128; off > 0; off >>= 1) {
        if (tid < off) red[tid] += red[tid + off];
        __syncthreads();
    }
    if (tid == 0) out[OUT_PERP] = expf(-red[0]);
}

// ---------------------------------------------------------------------------
extern "C" void kernel_launch(void* const* d_in, const int* in_sizes, int n_in,
                              void* d_out, int out_size) {
    const float* z = (const float*)d_in[0];        // (8, 64, 4096) f32
    const float* E = (const float*)d_in[1];        // (8192, 64) f32
    float* out = (float*)d_out;

    vq_prep      <<<32, 256>>>(E);
    vq_prep_bfrag<<<512, 256>>>(E);
    vq_scan      <<<128, 256>>>(z);
    vq_verify    <<<NPTS / 8, 256>>>(z, E);
    vq_gather    <<<2048, 256>>>(z, E, out);
    vq_hist      <<<NPTS / 256, 256>>>(out);
    vq_final     <<<1, 256>>>(out);
}